// round 1
// baseline (speedup 1.0000x reference)
#include <cuda_runtime.h>
#include <cuda_bf16.h>
#include <math.h>

// Problem constants
#define BB   2
#define SS   2048
#define HH   16
#define DD   64
#define HID  1024
#define MM   (BB*SS)        // 4096
#define BH   (BB*HH)        // 32

// Scratch (device globals; allocation-guard safe)
__device__ float g_q[BH * SS * DD];        // 16 MB  [bh][s][d]
__device__ float g_k[BH * SS * DD];        // 16 MB
__device__ float g_v[BH * SS * DD];        // 16 MB
__device__ float g_scores[(size_t)BH * SS * SS];  // 512 MB [bh][q][k]
__device__ float g_ctx[MM * HID];          // 16 MB  [b*S+s][h*64+d] (flat, ready for out-proj)

// ----------------------------------------------------------------------------
// Fused QKV projection: C = X @ W + b, written into [bh][s][d] head layout.
// 128x128x16 tiling, 8x8 per thread, 256 threads.
// grid: (HID/128, MM/128, 3)   z selects q/k/v
// ----------------------------------------------------------------------------
__global__ __launch_bounds__(256) void qkv_kernel(
    const float* __restrict__ X,
    const float* __restrict__ Wq, const float* __restrict__ bq,
    const float* __restrict__ Wk, const float* __restrict__ bk,
    const float* __restrict__ Wv, const float* __restrict__ bv)
{
    const int z = blockIdx.z;
    const float* __restrict__ W    = (z == 0) ? Wq : (z == 1) ? Wk : Wv;
    const float* __restrict__ bias = (z == 0) ? bq : (z == 1) ? bk : bv;
    float* __restrict__ dst        = (z == 0) ? g_q : (z == 1) ? g_k : g_v;

    __shared__ float As[16][128];
    __shared__ float Bs[16][128];

    const int m0 = blockIdx.y * 128;
    const int n0 = blockIdx.x * 128;
    const int tid = threadIdx.x;
    const int tx = tid & 15;     // column group (8 cols)
    const int ty = tid >> 4;     // row group (8 rows)

    float acc[8][8];
#pragma unroll
    for (int r = 0; r < 8; r++)
#pragma unroll
        for (int c = 0; c < 8; c++) acc[r][c] = 0.0f;

    for (int k0 = 0; k0 < HID; k0 += 16) {
        // A tile: 128 rows x 16 k  (transposed into As[k][m])
        for (int i = tid; i < 128 * 4; i += 256) {
            int row = i >> 2, k4 = i & 3;
            float4 v = *(const float4*)(X + (size_t)(m0 + row) * HID + k0 + k4 * 4);
            As[k4 * 4 + 0][row] = v.x;
            As[k4 * 4 + 1][row] = v.y;
            As[k4 * 4 + 2][row] = v.z;
            As[k4 * 4 + 3][row] = v.w;
        }
        // B tile: 16 k x 128 n
        for (int i = tid; i < 16 * 32; i += 256) {
            int kk = i >> 5, n4 = i & 31;
            *(float4*)(&Bs[kk][n4 * 4]) =
                *(const float4*)(W + (size_t)(k0 + kk) * HID + n0 + n4 * 4);
        }
        __syncthreads();
#pragma unroll
        for (int kk = 0; kk < 16; kk++) {
            float a[8], b[8];
            *(float4*)(&a[0]) = *(const float4*)(&As[kk][ty * 8]);
            *(float4*)(&a[4]) = *(const float4*)(&As[kk][ty * 8 + 4]);
            *(float4*)(&b[0]) = *(const float4*)(&Bs[kk][tx * 8]);
            *(float4*)(&b[4]) = *(const float4*)(&Bs[kk][tx * 8 + 4]);
#pragma unroll
            for (int r = 0; r < 8; r++)
#pragma unroll
                for (int c = 0; c < 8; c++)
                    acc[r][c] = fmaf(a[r], b[c], acc[r][c]);
        }
        __syncthreads();
    }

    // Epilogue: +bias, scatter to head layout [bh][s][d]
#pragma unroll
    for (int r = 0; r < 8; r++) {
        int m = m0 + ty * 8 + r;
        int b = m >> 11, s = m & 2047;
#pragma unroll
        for (int c = 0; c < 8; c++) {
            int n = n0 + tx * 8 + c;
            int h = n >> 6, d = n & 63;
            dst[(((size_t)((b << 4) + h)) * SS + s) * DD + d] = acc[r][c] + bias[n];
        }
    }
}

// ----------------------------------------------------------------------------
// Axial RoPE (in-place on g_q and g_k).
// Reference semantics: pairs are ADJACENT elements (2i,2i+1), but sin/cos freq
// index is (j mod half) — the two pair members use DIFFERENT frequencies.
// Segments: [0,20)->frame, [20,40)->height, [40,60)->width, [60,64) untouched.
// One thread handles one pair. Work = 2 tensors * 32 * 2048 rows * 30 pairs.
// ----------------------------------------------------------------------------
__global__ __launch_bounds__(256) void rope_kernel()
{
    int idx = blockIdx.x * 256 + threadIdx.x;
    const int total = 2 * BH * SS * 30;
    if (idx >= total) return;

    int pair  = idx % 30;
    int rowid = idx / 30;
    int s  = rowid & 2047;
    int r2 = rowid >> 11;
    int bh = r2 & 31;
    int t  = r2 >> 5;   // 0 = q, 1 = k

    float* base = ((t == 0) ? g_q : g_k) + ((size_t)bh * SS + s) * DD;

    int seg = pair / 10;
    int i   = pair - seg * 10;
    int j0  = seg * 20 + 2 * i;

    int posv = (seg == 0) ? (s >> 8) : ((seg == 1) ? ((s >> 4) & 15) : (s & 15));
    float p = (float)posv;

    int l0 = (2 * i) % 10;
    int l1 = (2 * i + 1) % 10;
    // omega_l = 10000^(-l/10) = exp(-l * ln(10000)/10)
    const float LN1E4_OVER_10 = 0.9210340371976184f;
    float om0 = expf(-LN1E4_OVER_10 * (float)l0);
    float om1 = expf(-LN1E4_OVER_10 * (float)l1);

    float x0 = base[j0], x1 = base[j0 + 1];
    float s0, c0, s1, c1;
    sincosf(p * om0, &s0, &c0);
    sincosf(p * om1, &s1, &c1);
    base[j0]     = x0 * c0 - x1 * s0;   // rot[2i]   = -x[2i+1]
    base[j0 + 1] = x1 * c1 + x0 * s1;   // rot[2i+1] =  x[2i]
}

// ----------------------------------------------------------------------------
// scores[bh] = (Q[bh] @ K[bh]^T) * 0.125     (batched, K-dim = 64)
// 128x128 tile, BK=16 (4 k-steps), 8x8 per thread.
// grid: (S/128, S/128, 32)
// ----------------------------------------------------------------------------
__global__ __launch_bounds__(256) void scores_kernel()
{
    const int bh = blockIdx.z;
    const float* __restrict__ Q  = g_q + (size_t)bh * SS * DD;
    const float* __restrict__ Kt = g_k + (size_t)bh * SS * DD;
    float* __restrict__ out = g_scores + (size_t)bh * SS * SS;

    __shared__ float As[16][128];
    __shared__ float Bs[16][128];

    const int m0 = blockIdx.y * 128;
    const int n0 = blockIdx.x * 128;
    const int tid = threadIdx.x;
    const int tx = tid & 15, ty = tid >> 4;

    float acc[8][8];
#pragma unroll
    for (int r = 0; r < 8; r++)
#pragma unroll
        for (int c = 0; c < 8; c++) acc[r][c] = 0.0f;

#pragma unroll
    for (int k0 = 0; k0 < DD; k0 += 16) {
        for (int i = tid; i < 128 * 4; i += 256) {
            int row = i >> 2, k4 = i & 3;
            float4 v = *(const float4*)(Q + (size_t)(m0 + row) * DD + k0 + k4 * 4);
            As[k4 * 4 + 0][row] = v.x;
            As[k4 * 4 + 1][row] = v.y;
            As[k4 * 4 + 2][row] = v.z;
            As[k4 * 4 + 3][row] = v.w;
        }
        for (int i = tid; i < 128 * 4; i += 256) {
            int row = i >> 2, k4 = i & 3;
            float4 v = *(const float4*)(Kt + (size_t)(n0 + row) * DD + k0 + k4 * 4);
            Bs[k4 * 4 + 0][row] = v.x;
            Bs[k4 * 4 + 1][row] = v.y;
            Bs[k4 * 4 + 2][row] = v.z;
            Bs[k4 * 4 + 3][row] = v.w;
        }
        __syncthreads();
#pragma unroll
        for (int kk = 0; kk < 16; kk++) {
            float a[8], b[8];
            *(float4*)(&a[0]) = *(const float4*)(&As[kk][ty * 8]);
            *(float4*)(&a[4]) = *(const float4*)(&As[kk][ty * 8 + 4]);
            *(float4*)(&b[0]) = *(const float4*)(&Bs[kk][tx * 8]);
            *(float4*)(&b[4]) = *(const float4*)(&Bs[kk][tx * 8 + 4]);
#pragma unroll
            for (int r = 0; r < 8; r++)
#pragma unroll
                for (int c = 0; c < 8; c++)
                    acc[r][c] = fmaf(a[r], b[c], acc[r][c]);
        }
        __syncthreads();
    }

#pragma unroll
    for (int r = 0; r < 8; r++) {
        int m = m0 + ty * 8 + r;
#pragma unroll
        for (int c = 0; c < 8; c++) {
            int n = n0 + tx * 8 + c;
            out[(size_t)m * SS + n] = acc[r][c] * 0.125f;
        }
    }
}

// ----------------------------------------------------------------------------
// Row softmax over 2048, in-place in g_scores. One block (256 thr) per row.
// ----------------------------------------------------------------------------
__global__ __launch_bounds__(256) void softmax_kernel()
{
    size_t row = blockIdx.x;
    float* __restrict__ p = g_scores + row * SS;
    const int tid = threadIdx.x;
    const int lane = tid & 31, warp = tid >> 5;

    __shared__ float red[8];
    __shared__ float bc;

    float v[8];
    float mx = -1e30f;
#pragma unroll
    for (int j = 0; j < 8; j++) {
        v[j] = p[tid + j * 256];
        mx = fmaxf(mx, v[j]);
    }
#pragma unroll
    for (int o = 16; o > 0; o >>= 1) mx = fmaxf(mx, __shfl_xor_sync(0xffffffffu, mx, o));
    if (lane == 0) red[warp] = mx;
    __syncthreads();
    if (tid == 0) {
        float m = red[0];
#pragma unroll
        for (int i = 1; i < 8; i++) m = fmaxf(m, red[i]);
        bc = m;
    }
    __syncthreads();
    mx = bc;

    float sum = 0.0f;
#pragma unroll
    for (int j = 0; j < 8; j++) {
        v[j] = expf(v[j] - mx);
        sum += v[j];
    }
#pragma unroll
    for (int o = 16; o > 0; o >>= 1) sum += __shfl_xor_sync(0xffffffffu, sum, o);
    if (lane == 0) red[warp] = sum;
    __syncthreads();
    if (tid == 0) {
        float t = 0.0f;
#pragma unroll
        for (int i = 0; i < 8; i++) t += red[i];
        bc = 1.0f / t;
    }
    __syncthreads();
    float inv = bc;
#pragma unroll
    for (int j = 0; j < 8; j++) p[tid + j * 256] = v[j] * inv;
}

// ----------------------------------------------------------------------------
// ctx[bh] = probs[bh] @ V[bh]   (M=2048, N=64, K=2048), written directly into
// the flat [b*S+s][h*64+d] layout for the output projection.
// BM=128, BN=64, BK=16, TM=8, TN=4, 256 threads. grid: (1, S/128, 32)
// ----------------------------------------------------------------------------
__global__ __launch_bounds__(256) void ctx_kernel()
{
    const int bh = blockIdx.z;
    const float* __restrict__ P = g_scores + (size_t)bh * SS * SS;
    const float* __restrict__ V = g_v + (size_t)bh * SS * DD;
    const int bb = bh >> 4, h = bh & 15;

    __shared__ float As[16][128];
    __shared__ float Bs[16][64];

    const int m0 = blockIdx.y * 128;
    const int tid = threadIdx.x;
    const int tx = tid & 15;   // col group (4 cols)
    const int ty = tid >> 4;   // row group (8 rows)

    float acc[8][4];
#pragma unroll
    for (int r = 0; r < 8; r++)
#pragma unroll
        for (int c = 0; c < 4; c++) acc[r][c] = 0.0f;

    for (int k0 = 0; k0 < SS; k0 += 16) {
        for (int i = tid; i < 128 * 4; i += 256) {
            int row = i >> 2, k4 = i & 3;
            float4 v = *(const float4*)(P + (size_t)(m0 + row) * SS + k0 + k4 * 4);
            As[k4 * 4 + 0][row] = v.x;
            As[k4 * 4 + 1][row] = v.y;
            As[k4 * 4 + 2][row] = v.z;
            As[k4 * 4 + 3][row] = v.w;
        }
        {
            int i = tid;  // 16*16 = 256 exactly
            int kk = i >> 4, n4 = i & 15;
            *(float4*)(&Bs[kk][n4 * 4]) =
                *(const float4*)(V + (size_t)(k0 + kk) * DD + n4 * 4);
        }
        __syncthreads();
#pragma unroll
        for (int kk = 0; kk < 16; kk++) {
            float a[8], b[4];
            *(float4*)(&a[0]) = *(const float4*)(&As[kk][ty * 8]);
            *(float4*)(&a[4]) = *(const float4*)(&As[kk][ty * 8 + 4]);
            *(float4*)(&b[0]) = *(const float4*)(&Bs[kk][tx * 4]);
#pragma unroll
            for (int r = 0; r < 8; r++)
#pragma unroll
                for (int c = 0; c < 4; c++)
                    acc[r][c] = fmaf(a[r], b[c], acc[r][c]);
        }
        __syncthreads();
    }

#pragma unroll
    for (int r = 0; r < 8; r++) {
        int s = m0 + ty * 8 + r;
#pragma unroll
        for (int c = 0; c < 4; c++) {
            int d = tx * 4 + c;
            g_ctx[((size_t)(bb * SS + s)) * HID + h * DD + d] = acc[r][c];
        }
    }
}

// ----------------------------------------------------------------------------
// Output projection: out = ctx_flat @ Wo + bo   (4096x1024x1024)
// grid: (HID/128, MM/128)
// ----------------------------------------------------------------------------
__global__ __launch_bounds__(256) void oproj_kernel(
    const float* __restrict__ Wo, const float* __restrict__ bo,
    float* __restrict__ out)
{
    __shared__ float As[16][128];
    __shared__ float Bs[16][128];

    const int m0 = blockIdx.y * 128;
    const int n0 = blockIdx.x * 128;
    const int tid = threadIdx.x;
    const int tx = tid & 15, ty = tid >> 4;

    float acc[8][8];
#pragma unroll
    for (int r = 0; r < 8; r++)
#pragma unroll
        for (int c = 0; c < 8; c++) acc[r][c] = 0.0f;

    for (int k0 = 0; k0 < HID; k0 += 16) {
        for (int i = tid; i < 128 * 4; i += 256) {
            int row = i >> 2, k4 = i & 3;
            float4 v = *(const float4*)(g_ctx + (size_t)(m0 + row) * HID + k0 + k4 * 4);
            As[k4 * 4 + 0][row] = v.x;
            As[k4 * 4 + 1][row] = v.y;
            As[k4 * 4 + 2][row] = v.z;
            As[k4 * 4 + 3][row] = v.w;
        }
        for (int i = tid; i < 16 * 32; i += 256) {
            int kk = i >> 5, n4 = i & 31;
            *(float4*)(&Bs[kk][n4 * 4]) =
                *(const float4*)(Wo + (size_t)(k0 + kk) * HID + n0 + n4 * 4);
        }
        __syncthreads();
#pragma unroll
        for (int kk = 0; kk < 16; kk++) {
            float a[8], b[8];
            *(float4*)(&a[0]) = *(const float4*)(&As[kk][ty * 8]);
            *(float4*)(&a[4]) = *(const float4*)(&As[kk][ty * 8 + 4]);
            *(float4*)(&b[0]) = *(const float4*)(&Bs[kk][tx * 8]);
            *(float4*)(&b[4]) = *(const float4*)(&Bs[kk][tx * 8 + 4]);
#pragma unroll
            for (int r = 0; r < 8; r++)
#pragma unroll
                for (int c = 0; c < 8; c++)
                    acc[r][c] = fmaf(a[r], b[c], acc[r][c]);
        }
        __syncthreads();
    }

#pragma unroll
    for (int r = 0; r < 8; r++) {
        int m = m0 + ty * 8 + r;
#pragma unroll
        for (int c = 0; c < 8; c++) {
            int n = n0 + tx * 8 + c;
            out[(size_t)m * HID + n] = acc[r][c] + bo[n];
        }
    }
}

// ----------------------------------------------------------------------------
extern "C" void kernel_launch(void* const* d_in, const int* in_sizes, int n_in,
                              void* d_out, int out_size)
{
    const float* X  = (const float*)d_in[0];
    const float* Wq = (const float*)d_in[1];
    const float* bq = (const float*)d_in[2];
    const float* Wk = (const float*)d_in[3];
    const float* bk = (const float*)d_in[4];
    const float* Wv = (const float*)d_in[5];
    const float* bv = (const float*)d_in[6];
    const float* Wo = (const float*)d_in[7];
    const float* bo = (const float*)d_in[8];
    float* out = (float*)d_out;

    // 1. QKV projections -> head layout
    qkv_kernel<<<dim3(HID / 128, MM / 128, 3), 256>>>(X, Wq, bq, Wk, bk, Wv, bv);

    // 2. Axial RoPE on q and k (in-place)
    {
        const int total = 2 * BH * SS * 30;
        rope_kernel<<<(total + 255) / 256, 256>>>();
    }

    // 3. scores = Q @ K^T * scale
    scores_kernel<<<dim3(SS / 128, SS / 128, BH), 256>>>();

    // 4. softmax rows
    softmax_kernel<<<BH * SS, 256>>>();

    // 5. ctx = probs @ V  (written into flat layout)
    ctx_kernel<<<dim3(1, SS / 128, BH), 256>>>();

    // 6. out = ctx @ Wo + bo
    oproj_kernel<<<dim3(HID / 128, MM / 128), 256>>>(Wo, bo, out);
}

// round 3
// speedup vs baseline: 2.6433x; 2.6433x over previous
#include <cuda_runtime.h>
#include <cuda_bf16.h>
#include <math.h>
#include <stdint.h>

// Problem constants
#define BB   2
#define SS   2048
#define HH   16
#define DD   64
#define HID  1024
#define MM   (BB*SS)        // 4096
#define BH   (BB*HH)        // 32

// Scratch (device globals; allocation-guard safe)
__device__ float g_q[BH * SS * DD];               // [bh][s][d]
__device__ float g_k[BH * SS * DD];
__device__ float g_v[BH * SS * DD];
__device__ float g_scores[(size_t)BH * SS * SS];  // 512 MB [bh][q][k]
__device__ float g_ctx[MM * HID];                 // [b*S+s][h*64+d]

// ----------------------------------------------------------------------------
// TF32 helpers
// ----------------------------------------------------------------------------
__device__ __forceinline__ uint32_t f2tf32(float x) {
    uint32_t r;
    asm("cvt.rna.tf32.f32 %0, %1;" : "=r"(r) : "f"(x));
    return r;
}

__device__ __forceinline__ void mma_tf32(float* d, const uint32_t* a, const uint32_t* b) {
    asm volatile(
        "mma.sync.aligned.m16n8k8.row.col.f32.tf32.tf32.f32 "
        "{%0,%1,%2,%3}, {%4,%5,%6,%7}, {%8,%9}, {%0,%1,%2,%3};"
        : "+f"(d[0]), "+f"(d[1]), "+f"(d[2]), "+f"(d[3])
        : "r"(a[0]), "r"(a[1]), "r"(a[2]), "r"(a[3]), "r"(b[0]), "r"(b[1]));
}

// ----------------------------------------------------------------------------
// QKV projection (TF32 MMA): C = X @ W + b  -> head layout [bh][s][d]
// BM=128, BN=128, BK=16. 8 warps: 4 (M) x 2 (N); warp tile 32x64.
// grid: (HID/128, MM/128, 3)
// ----------------------------------------------------------------------------
__global__ __launch_bounds__(256) void qkv_mma_kernel(
    const float* __restrict__ X,
    const float* __restrict__ Wq, const float* __restrict__ bq,
    const float* __restrict__ Wk, const float* __restrict__ bk,
    const float* __restrict__ Wv, const float* __restrict__ bv)
{
    const int z = blockIdx.z;
    const float* __restrict__ W    = (z == 0) ? Wq : (z == 1) ? Wk : Wv;
    const float* __restrict__ bias = (z == 0) ? bq : (z == 1) ? bk : bv;
    float* __restrict__ dst        = (z == 0) ? g_q : (z == 1) ? g_k : g_v;

    __shared__ uint32_t As[128][20];    // [m][k], pad->conflict-free frags
    __shared__ uint32_t Bs[16][136];    // [k][n]

    const int m0 = blockIdx.y * 128;
    const int n0 = blockIdx.x * 128;
    const int tid = threadIdx.x;
    const int wid = tid >> 5, lane = tid & 31;
    const int g = lane >> 2, t = lane & 3;
    const int wm = wid >> 1, wn = wid & 1;   // 4 x 2 warp grid

    float acc[2][8][4];
#pragma unroll
    for (int i = 0; i < 2; i++)
#pragma unroll
        for (int j = 0; j < 8; j++)
#pragma unroll
            for (int r = 0; r < 4; r++) acc[i][j][r] = 0.0f;

    for (int k0 = 0; k0 < HID; k0 += 16) {
        // A tile: 128x16
#pragma unroll
        for (int i = tid; i < 512; i += 256) {
            int row = i >> 2, c4 = (i & 3) * 4;
            float4 v = *(const float4*)(X + (size_t)(m0 + row) * HID + k0 + c4);
            As[row][c4 + 0] = f2tf32(v.x);
            As[row][c4 + 1] = f2tf32(v.y);
            As[row][c4 + 2] = f2tf32(v.z);
            As[row][c4 + 3] = f2tf32(v.w);
        }
        // B tile: 16x128
#pragma unroll
        for (int i = tid; i < 512; i += 256) {
            int kk = i >> 5, n4 = (i & 31) * 4;
            float4 v = *(const float4*)(W + (size_t)(k0 + kk) * HID + n0 + n4);
            Bs[kk][n4 + 0] = f2tf32(v.x);
            Bs[kk][n4 + 1] = f2tf32(v.y);
            Bs[kk][n4 + 2] = f2tf32(v.z);
            Bs[kk][n4 + 3] = f2tf32(v.w);
        }
        __syncthreads();

#pragma unroll
        for (int ks = 0; ks < 2; ks++) {
            const int kb = ks * 8;
            uint32_t a[2][4], b[8][2];
#pragma unroll
            for (int ma = 0; ma < 2; ma++) {
                int row = wm * 32 + ma * 16 + g;
                a[ma][0] = As[row][kb + t];
                a[ma][1] = As[row + 8][kb + t];
                a[ma][2] = As[row][kb + t + 4];
                a[ma][3] = As[row + 8][kb + t + 4];
            }
#pragma unroll
            for (int na = 0; na < 8; na++) {
                int n = wn * 64 + na * 8 + g;
                b[na][0] = Bs[kb + t][n];
                b[na][1] = Bs[kb + t + 4][n];
            }
#pragma unroll
            for (int ma = 0; ma < 2; ma++)
#pragma unroll
                for (int na = 0; na < 8; na++)
                    mma_tf32(acc[ma][na], a[ma], b[na]);
        }
        __syncthreads();
    }

    // Epilogue: +bias, scatter to [bh][s][d]
#pragma unroll
    for (int ma = 0; ma < 2; ma++) {
#pragma unroll
        for (int na = 0; na < 8; na++) {
            int m = m0 + wm * 32 + ma * 16 + g;
            int n = n0 + wn * 64 + na * 8 + 2 * t;
            float b0 = bias[n], b1 = bias[n + 1];
            int h = n >> 6, d = n & 63;
            {
                int b = m >> 11, s = m & 2047;
                float2 v = { acc[ma][na][0] + b0, acc[ma][na][1] + b1 };
                *(float2*)(dst + (((size_t)((b << 4) + h)) * SS + s) * DD + d) = v;
            }
            {
                int m2 = m + 8;
                int b = m2 >> 11, s = m2 & 2047;
                float2 v = { acc[ma][na][2] + b0, acc[ma][na][3] + b1 };
                *(float2*)(dst + (((size_t)((b << 4) + h)) * SS + s) * DD + d) = v;
            }
        }
    }
}

// ----------------------------------------------------------------------------
// Axial RoPE (in-place on g_q and g_k), reference-exact semantics.
// ----------------------------------------------------------------------------
__global__ __launch_bounds__(256) void rope_kernel()
{
    int idx = blockIdx.x * 256 + threadIdx.x;
    const int total = 2 * BH * SS * 30;
    if (idx >= total) return;

    int pair  = idx % 30;
    int rowid = idx / 30;
    int s  = rowid & 2047;
    int r2 = rowid >> 11;
    int bh = r2 & 31;
    int t  = r2 >> 5;

    float* base = ((t == 0) ? g_q : g_k) + ((size_t)bh * SS + s) * DD;

    int seg = pair / 10;
    int i   = pair - seg * 10;
    int j0  = seg * 20 + 2 * i;

    int posv = (seg == 0) ? (s >> 8) : ((seg == 1) ? ((s >> 4) & 15) : (s & 15));
    float p = (float)posv;

    int l0 = (2 * i) % 10;
    int l1 = (2 * i + 1) % 10;
    const float LN1E4_OVER_10 = 0.9210340371976184f;
    float om0 = expf(-LN1E4_OVER_10 * (float)l0);
    float om1 = expf(-LN1E4_OVER_10 * (float)l1);

    float x0 = base[j0], x1 = base[j0 + 1];
    float s0, c0, s1, c1;
    sincosf(p * om0, &s0, &c0);
    sincosf(p * om1, &s1, &c1);
    base[j0]     = x0 * c0 - x1 * s0;
    base[j0 + 1] = x1 * c1 + x0 * s1;
}

// ----------------------------------------------------------------------------
// scores[bh] = (Q @ K^T) * 0.125 (TF32 MMA). M=N=2048, K=64.
// BM=128, BN=128, BK=16. Warp grid 4x2, warp tile 32x64.
// grid: (16, 16, 32)
// ----------------------------------------------------------------------------
__global__ __launch_bounds__(256) void scores_mma_kernel()
{
    const int bh = blockIdx.z;
    const float* __restrict__ Q  = g_q + (size_t)bh * SS * DD;
    const float* __restrict__ Kt = g_k + (size_t)bh * SS * DD;
    float* __restrict__ out = g_scores + (size_t)bh * SS * SS;

    __shared__ uint32_t As[128][20];   // [m][k]
    __shared__ uint32_t Bs[128][20];   // [n][k]

    const int m0 = blockIdx.y * 128;
    const int n0 = blockIdx.x * 128;
    const int tid = threadIdx.x;
    const int wid = tid >> 5, lane = tid & 31;
    const int g = lane >> 2, t = lane & 3;
    const int wm = wid >> 1, wn = wid & 1;

    float acc[2][8][4];
#pragma unroll
    for (int i = 0; i < 2; i++)
#pragma unroll
        for (int j = 0; j < 8; j++)
#pragma unroll
            for (int r = 0; r < 4; r++) acc[i][j][r] = 0.0f;

#pragma unroll
    for (int k0 = 0; k0 < DD; k0 += 16) {
#pragma unroll
        for (int i = tid; i < 512; i += 256) {
            int row = i >> 2, c4 = (i & 3) * 4;
            float4 v = *(const float4*)(Q + (size_t)(m0 + row) * DD + k0 + c4);
            As[row][c4 + 0] = f2tf32(v.x);
            As[row][c4 + 1] = f2tf32(v.y);
            As[row][c4 + 2] = f2tf32(v.z);
            As[row][c4 + 3] = f2tf32(v.w);
        }
#pragma unroll
        for (int i = tid; i < 512; i += 256) {
            int row = i >> 2, c4 = (i & 3) * 4;
            float4 v = *(const float4*)(Kt + (size_t)(n0 + row) * DD + k0 + c4);
            Bs[row][c4 + 0] = f2tf32(v.x);
            Bs[row][c4 + 1] = f2tf32(v.y);
            Bs[row][c4 + 2] = f2tf32(v.z);
            Bs[row][c4 + 3] = f2tf32(v.w);
        }
        __syncthreads();

#pragma unroll
        for (int ks = 0; ks < 2; ks++) {
            const int kb = ks * 8;
            uint32_t a[2][4], b[8][2];
#pragma unroll
            for (int ma = 0; ma < 2; ma++) {
                int row = wm * 32 + ma * 16 + g;
                a[ma][0] = As[row][kb + t];
                a[ma][1] = As[row + 8][kb + t];
                a[ma][2] = As[row][kb + t + 4];
                a[ma][3] = As[row + 8][kb + t + 4];
            }
#pragma unroll
            for (int na = 0; na < 8; na++) {
                int n = wn * 64 + na * 8 + g;
                b[na][0] = Bs[n][kb + t];
                b[na][1] = Bs[n][kb + t + 4];
            }
#pragma unroll
            for (int ma = 0; ma < 2; ma++)
#pragma unroll
                for (int na = 0; na < 8; na++)
                    mma_tf32(acc[ma][na], a[ma], b[na]);
        }
        __syncthreads();
    }

#pragma unroll
    for (int ma = 0; ma < 2; ma++) {
#pragma unroll
        for (int na = 0; na < 8; na++) {
            int m = m0 + wm * 32 + ma * 16 + g;
            int n = n0 + wn * 64 + na * 8 + 2 * t;
            float2 v0 = { acc[ma][na][0] * 0.125f, acc[ma][na][1] * 0.125f };
            float2 v1 = { acc[ma][na][2] * 0.125f, acc[ma][na][3] * 0.125f };
            *(float2*)(out + (size_t)m * SS + n) = v0;
            *(float2*)(out + (size_t)(m + 8) * SS + n) = v1;
        }
    }
}

// ----------------------------------------------------------------------------
// Row softmax over 2048, in-place. One block (256 thr) per row.
// ----------------------------------------------------------------------------
__global__ __launch_bounds__(256) void softmax_kernel()
{
    size_t row = blockIdx.x;
    float* __restrict__ p = g_scores + row * SS;
    const int tid = threadIdx.x;
    const int lane = tid & 31, warp = tid >> 5;

    __shared__ float red[8];
    __shared__ float bc;

    float v[8];
    float mx = -1e30f;
#pragma unroll
    for (int j = 0; j < 8; j++) {
        v[j] = p[tid + j * 256];
        mx = fmaxf(mx, v[j]);
    }
#pragma unroll
    for (int o = 16; o > 0; o >>= 1) mx = fmaxf(mx, __shfl_xor_sync(0xffffffffu, mx, o));
    if (lane == 0) red[warp] = mx;
    __syncthreads();
    if (tid == 0) {
        float m = red[0];
#pragma unroll
        for (int i = 1; i < 8; i++) m = fmaxf(m, red[i]);
        bc = m;
    }
    __syncthreads();
    mx = bc;

    float sum = 0.0f;
#pragma unroll
    for (int j = 0; j < 8; j++) {
        v[j] = expf(v[j] - mx);
        sum += v[j];
    }
#pragma unroll
    for (int o = 16; o > 0; o >>= 1) sum += __shfl_xor_sync(0xffffffffu, sum, o);
    if (lane == 0) red[warp] = sum;
    __syncthreads();
    if (tid == 0) {
        float tt = 0.0f;
#pragma unroll
        for (int i = 0; i < 8; i++) tt += red[i];
        bc = 1.0f / tt;
    }
    __syncthreads();
    float inv = bc;
#pragma unroll
    for (int j = 0; j < 8; j++) p[tid + j * 256] = v[j] * inv;
}

// ----------------------------------------------------------------------------
// ctx[bh] = probs @ V (TF32 MMA). M=2048, N=64, K=2048.
// BM=128, BN=64, BK=32. Warp grid 4x2, warp tile 32x32.
// grid: (1, 16, 32)
// ----------------------------------------------------------------------------
__global__ __launch_bounds__(256) void ctx_mma_kernel()
{
    const int bh = blockIdx.z;
    const float* __restrict__ P = g_scores + (size_t)bh * SS * SS;
    const float* __restrict__ V = g_v + (size_t)bh * SS * DD;
    const int bb = bh >> 4, h = bh & 15;

    __shared__ uint32_t As[128][36];   // [m][k], BK=32
    __shared__ uint32_t Bs[32][72];    // [k][n]

    const int m0 = blockIdx.y * 128;
    const int tid = threadIdx.x;
    const int wid = tid >> 5, lane = tid & 31;
    const int g = lane >> 2, t = lane & 3;
    const int wm = wid >> 1, wn = wid & 1;

    float acc[2][4][4];
#pragma unroll
    for (int i = 0; i < 2; i++)
#pragma unroll
        for (int j = 0; j < 4; j++)
#pragma unroll
            for (int r = 0; r < 4; r++) acc[i][j][r] = 0.0f;

    for (int k0 = 0; k0 < SS; k0 += 32) {
        // A tile: 128x32 (1024 float4)
#pragma unroll
        for (int i = tid; i < 1024; i += 256) {
            int row = i >> 3, c4 = (i & 7) * 4;
            float4 v = *(const float4*)(P + (size_t)(m0 + row) * SS + k0 + c4);
            As[row][c4 + 0] = f2tf32(v.x);
            As[row][c4 + 1] = f2tf32(v.y);
            As[row][c4 + 2] = f2tf32(v.z);
            As[row][c4 + 3] = f2tf32(v.w);
        }
        // B tile: 32x64 (512 float4)
#pragma unroll
        for (int i = tid; i < 512; i += 256) {
            int kk = i >> 4, n4 = (i & 15) * 4;
            float4 v = *(const float4*)(V + (size_t)(k0 + kk) * DD + n4);
            Bs[kk][n4 + 0] = f2tf32(v.x);
            Bs[kk][n4 + 1] = f2tf32(v.y);
            Bs[kk][n4 + 2] = f2tf32(v.z);
            Bs[kk][n4 + 3] = f2tf32(v.w);
        }
        __syncthreads();

#pragma unroll
        for (int ks = 0; ks < 4; ks++) {
            const int kb = ks * 8;
            uint32_t a[2][4], b[4][2];
#pragma unroll
            for (int ma = 0; ma < 2; ma++) {
                int row = wm * 32 + ma * 16 + g;
                a[ma][0] = As[row][kb + t];
                a[ma][1] = As[row + 8][kb + t];
                a[ma][2] = As[row][kb + t + 4];
                a[ma][3] = As[row + 8][kb + t + 4];
            }
#pragma unroll
            for (int na = 0; na < 4; na++) {
                int n = wn * 32 + na * 8 + g;
                b[na][0] = Bs[kb + t][n];
                b[na][1] = Bs[kb + t + 4][n];
            }
#pragma unroll
            for (int ma = 0; ma < 2; ma++)
#pragma unroll
                for (int na = 0; na < 4; na++)
                    mma_tf32(acc[ma][na], a[ma], b[na]);
        }
        __syncthreads();
    }

#pragma unroll
    for (int ma = 0; ma < 2; ma++) {
#pragma unroll
        for (int na = 0; na < 4; na++) {
            int s = m0 + wm * 32 + ma * 16 + g;
            int d = wn * 32 + na * 8 + 2 * t;
            float2 v0 = { acc[ma][na][0], acc[ma][na][1] };
            float2 v1 = { acc[ma][na][2], acc[ma][na][3] };
            *(float2*)(g_ctx + ((size_t)(bb * SS + s)) * HID + h * DD + d) = v0;
            *(float2*)(g_ctx + ((size_t)(bb * SS + s + 8)) * HID + h * DD + d) = v1;
        }
    }
}

// ----------------------------------------------------------------------------
// Output projection (TF32 MMA): out = ctx @ Wo + bo. M=4096, N=1024, K=1024.
// grid: (8, 32)
// ----------------------------------------------------------------------------
__global__ __launch_bounds__(256) void oproj_mma_kernel(
    const float* __restrict__ Wo, const float* __restrict__ bo,
    float* __restrict__ out)
{
    __shared__ uint32_t As[128][20];
    __shared__ uint32_t Bs[16][136];

    const int m0 = blockIdx.y * 128;
    const int n0 = blockIdx.x * 128;
    const int tid = threadIdx.x;
    const int wid = tid >> 5, lane = tid & 31;
    const int g = lane >> 2, t = lane & 3;
    const int wm = wid >> 1, wn = wid & 1;

    float acc[2][8][4];
#pragma unroll
    for (int i = 0; i < 2; i++)
#pragma unroll
        for (int j = 0; j < 8; j++)
#pragma unroll
            for (int r = 0; r < 4; r++) acc[i][j][r] = 0.0f;

    for (int k0 = 0; k0 < HID; k0 += 16) {
#pragma unroll
        for (int i = tid; i < 512; i += 256) {
            int row = i >> 2, c4 = (i & 3) * 4;
            float4 v = *(const float4*)(g_ctx + (size_t)(m0 + row) * HID + k0 + c4);
            As[row][c4 + 0] = f2tf32(v.x);
            As[row][c4 + 1] = f2tf32(v.y);
            As[row][c4 + 2] = f2tf32(v.z);
            As[row][c4 + 3] = f2tf32(v.w);
        }
#pragma unroll
        for (int i = tid; i < 512; i += 256) {
            int kk = i >> 5, n4 = (i & 31) * 4;
            float4 v = *(const float4*)(Wo + (size_t)(k0 + kk) * HID + n0 + n4);
            Bs[kk][n4 + 0] = f2tf32(v.x);
            Bs[kk][n4 + 1] = f2tf32(v.y);
            Bs[kk][n4 + 2] = f2tf32(v.z);
            Bs[kk][n4 + 3] = f2tf32(v.w);
        }
        __syncthreads();

#pragma unroll
        for (int ks = 0; ks < 2; ks++) {
            const int kb = ks * 8;
            uint32_t a[2][4], b[8][2];
#pragma unroll
            for (int ma = 0; ma < 2; ma++) {
                int row = wm * 32 + ma * 16 + g;
                a[ma][0] = As[row][kb + t];
                a[ma][1] = As[row + 8][kb + t];
                a[ma][2] = As[row][kb + t + 4];
                a[ma][3] = As[row + 8][kb + t + 4];
            }
#pragma unroll
            for (int na = 0; na < 8; na++) {
                int n = wn * 64 + na * 8 + g;
                b[na][0] = Bs[kb + t][n];
                b[na][1] = Bs[kb + t + 4][n];
            }
#pragma unroll
            for (int ma = 0; ma < 2; ma++)
#pragma unroll
                for (int na = 0; na < 8; na++)
                    mma_tf32(acc[ma][na], a[ma], b[na]);
        }
        __syncthreads();
    }

#pragma unroll
    for (int ma = 0; ma < 2; ma++) {
#pragma unroll
        for (int na = 0; na < 8; na++) {
            int m = m0 + wm * 32 + ma * 16 + g;
            int n = n0 + wn * 64 + na * 8 + 2 * t;
            float b0 = bo[n], b1 = bo[n + 1];
            float2 v0 = { acc[ma][na][0] + b0, acc[ma][na][1] + b1 };
            float2 v1 = { acc[ma][na][2] + b0, acc[ma][na][3] + b1 };
            *(float2*)(out + (size_t)m * HID + n) = v0;
            *(float2*)(out + (size_t)(m + 8) * HID + n) = v1;
        }
    }
}

// ----------------------------------------------------------------------------
extern "C" void kernel_launch(void* const* d_in, const int* in_sizes, int n_in,
                              void* d_out, int out_size)
{
    const float* X  = (const float*)d_in[0];
    const float* Wq = (const float*)d_in[1];
    const float* bq = (const float*)d_in[2];
    const float* Wk = (const float*)d_in[3];
    const float* bk = (const float*)d_in[4];
    const float* Wv = (const float*)d_in[5];
    const float* bv = (const float*)d_in[6];
    const float* Wo = (const float*)d_in[7];
    const float* bo = (const float*)d_in[8];
    float* out = (float*)d_out;

    qkv_mma_kernel<<<dim3(HID / 128, MM / 128, 3), 256>>>(X, Wq, bq, Wk, bk, Wv, bv);

    {
        const int total = 2 * BH * SS * 30;
        rope_kernel<<<(total + 255) / 256, 256>>>();
    }

    scores_mma_kernel<<<dim3(SS / 128, SS / 128, BH), 256>>>();

    softmax_kernel<<<BH * SS, 256>>>();

    ctx_mma_kernel<<<dim3(1, SS / 128, BH), 256>>>();

    oproj_mma_kernel<<<dim3(HID / 128, MM / 128), 256>>>(Wo, bo, out);
}

// round 4
// speedup vs baseline: 4.1447x; 1.5680x over previous
#include <cuda_runtime.h>
#include <cuda_bf16.h>
#include <math.h>
#include <stdint.h>

// Problem constants
#define BB   2
#define SS   2048
#define HH   16
#define DD   64
#define HID  1024
#define MM   (BB*SS)        // 4096
#define BH   (BB*HH)        // 32

// Scratch (device globals; allocation-guard safe)
__device__ float g_q[BH * SS * DD];   // [bh][s][d]
__device__ float g_k[BH * SS * DD];
__device__ float g_v[BH * SS * DD];
__device__ float g_ctx[MM * HID];     // [b*S+s][h*64+d]

// ----------------------------------------------------------------------------
// TF32 helpers
// ----------------------------------------------------------------------------
__device__ __forceinline__ uint32_t f2tf32(float x) {
    uint32_t r;
    asm("cvt.rna.tf32.f32 %0, %1;" : "=r"(r) : "f"(x));
    return r;
}

__device__ __forceinline__ void mma_tf32(float* d, const uint32_t* a, const uint32_t* b) {
    asm volatile(
        "mma.sync.aligned.m16n8k8.row.col.f32.tf32.tf32.f32 "
        "{%0,%1,%2,%3}, {%4,%5,%6,%7}, {%8,%9}, {%0,%1,%2,%3};"
        : "+f"(d[0]), "+f"(d[1]), "+f"(d[2]), "+f"(d[3])
        : "r"(a[0]), "r"(a[1]), "r"(a[2]), "r"(a[3]), "r"(b[0]), "r"(b[1]));
}

// ----------------------------------------------------------------------------
// QKV projection (TF32 MMA): C = X @ W + b  -> head layout [bh][s][d]
// BM=128, BN=128, BK=16. Warp grid 4x2, warp tile 32x64.
// ----------------------------------------------------------------------------
__global__ __launch_bounds__(256) void qkv_mma_kernel(
    const float* __restrict__ X,
    const float* __restrict__ Wq, const float* __restrict__ bq,
    const float* __restrict__ Wk, const float* __restrict__ bk,
    const float* __restrict__ Wv, const float* __restrict__ bv)
{
    const int z = blockIdx.z;
    const float* __restrict__ W    = (z == 0) ? Wq : (z == 1) ? Wk : Wv;
    const float* __restrict__ bias = (z == 0) ? bq : (z == 1) ? bk : bv;
    float* __restrict__ dst        = (z == 0) ? g_q : (z == 1) ? g_k : g_v;

    __shared__ uint32_t As[128][20];
    __shared__ uint32_t Bs[16][136];

    const int m0 = blockIdx.y * 128;
    const int n0 = blockIdx.x * 128;
    const int tid = threadIdx.x;
    const int wid = tid >> 5, lane = tid & 31;
    const int g = lane >> 2, t = lane & 3;
    const int wm = wid >> 1, wn = wid & 1;

    float acc[2][8][4];
#pragma unroll
    for (int i = 0; i < 2; i++)
#pragma unroll
        for (int j = 0; j < 8; j++)
#pragma unroll
            for (int r = 0; r < 4; r++) acc[i][j][r] = 0.0f;

    for (int k0 = 0; k0 < HID; k0 += 16) {
#pragma unroll
        for (int i = tid; i < 512; i += 256) {
            int row = i >> 2, c4 = (i & 3) * 4;
            float4 v = *(const float4*)(X + (size_t)(m0 + row) * HID + k0 + c4);
            As[row][c4 + 0] = f2tf32(v.x);
            As[row][c4 + 1] = f2tf32(v.y);
            As[row][c4 + 2] = f2tf32(v.z);
            As[row][c4 + 3] = f2tf32(v.w);
        }
#pragma unroll
        for (int i = tid; i < 512; i += 256) {
            int kk = i >> 5, n4 = (i & 31) * 4;
            float4 v = *(const float4*)(W + (size_t)(k0 + kk) * HID + n0 + n4);
            Bs[kk][n4 + 0] = f2tf32(v.x);
            Bs[kk][n4 + 1] = f2tf32(v.y);
            Bs[kk][n4 + 2] = f2tf32(v.z);
            Bs[kk][n4 + 3] = f2tf32(v.w);
        }
        __syncthreads();

#pragma unroll
        for (int ks = 0; ks < 2; ks++) {
            const int kb = ks * 8;
            uint32_t a[2][4], b[8][2];
#pragma unroll
            for (int ma = 0; ma < 2; ma++) {
                int row = wm * 32 + ma * 16 + g;
                a[ma][0] = As[row][kb + t];
                a[ma][1] = As[row + 8][kb + t];
                a[ma][2] = As[row][kb + t + 4];
                a[ma][3] = As[row + 8][kb + t + 4];
            }
#pragma unroll
            for (int na = 0; na < 8; na++) {
                int n = wn * 64 + na * 8 + g;
                b[na][0] = Bs[kb + t][n];
                b[na][1] = Bs[kb + t + 4][n];
            }
#pragma unroll
            for (int ma = 0; ma < 2; ma++)
#pragma unroll
                for (int na = 0; na < 8; na++)
                    mma_tf32(acc[ma][na], a[ma], b[na]);
        }
        __syncthreads();
    }

#pragma unroll
    for (int ma = 0; ma < 2; ma++) {
#pragma unroll
        for (int na = 0; na < 8; na++) {
            int m = m0 + wm * 32 + ma * 16 + g;
            int n = n0 + wn * 64 + na * 8 + 2 * t;
            float b0 = bias[n], b1 = bias[n + 1];
            int h = n >> 6, d = n & 63;
            {
                int b = m >> 11, s = m & 2047;
                float2 v = { acc[ma][na][0] + b0, acc[ma][na][1] + b1 };
                *(float2*)(dst + (((size_t)((b << 4) + h)) * SS + s) * DD + d) = v;
            }
            {
                int m2 = m + 8;
                int b = m2 >> 11, s = m2 & 2047;
                float2 v = { acc[ma][na][2] + b0, acc[ma][na][3] + b1 };
                *(float2*)(dst + (((size_t)((b << 4) + h)) * SS + s) * DD + d) = v;
            }
        }
    }
}

// ----------------------------------------------------------------------------
// Axial RoPE (in-place on g_q and g_k), reference-exact semantics.
// ----------------------------------------------------------------------------
__global__ __launch_bounds__(256) void rope_kernel()
{
    int idx = blockIdx.x * 256 + threadIdx.x;
    const int total = 2 * BH * SS * 30;
    if (idx >= total) return;

    int pair  = idx % 30;
    int rowid = idx / 30;
    int s  = rowid & 2047;
    int r2 = rowid >> 11;
    int bh = r2 & 31;
    int t  = r2 >> 5;

    float* base = ((t == 0) ? g_q : g_k) + ((size_t)bh * SS + s) * DD;

    int seg = pair / 10;
    int i   = pair - seg * 10;
    int j0  = seg * 20 + 2 * i;

    int posv = (seg == 0) ? (s >> 8) : ((seg == 1) ? ((s >> 4) & 15) : (s & 15));
    float p = (float)posv;

    int l0 = (2 * i) % 10;
    int l1 = (2 * i + 1) % 10;
    const float LN1E4_OVER_10 = 0.9210340371976184f;
    float om0 = expf(-LN1E4_OVER_10 * (float)l0);
    float om1 = expf(-LN1E4_OVER_10 * (float)l1);

    float x0 = base[j0], x1 = base[j0 + 1];
    float s0, c0, s1, c1;
    sincosf(p * om0, &s0, &c0);
    sincosf(p * om1, &s1, &c1);
    base[j0]     = x0 * c0 - x1 * s0;
    base[j0 + 1] = x1 * c1 + x0 * s1;
}

// ----------------------------------------------------------------------------
// Fused flash attention: softmax(Q K^T * 0.125) @ V  -> g_ctx (flat layout).
// Block = one (bh, 128-row Q tile). 8 warps, each owns 16 complete rows.
// K-tile = 64 keys per iteration (32 iterations).
// Smem: Q[128x64] tf32, K[64x64] tf32, V[64x64] tf32, P[128x64] tf32.
// grid: (SS/128, BH), 256 threads, ~105 KB dynamic smem.
// ----------------------------------------------------------------------------
#define QS_STR 68
#define KS_STR 68
#define VS_STR 72
#define PS_STR 68
#define SM_Q 0
#define SM_K (SM_Q + 128 * QS_STR)
#define SM_V (SM_K + 64 * KS_STR)
#define SM_P (SM_V + 64 * VS_STR)
#define FLASH_SMEM_WORDS (SM_P + 128 * PS_STR)
#define FLASH_SMEM_BYTES (FLASH_SMEM_WORDS * 4)

__global__ __launch_bounds__(256) void flash_kernel()
{
    extern __shared__ uint32_t sm[];
    uint32_t* __restrict__ Qs = sm + SM_Q;
    uint32_t* __restrict__ Ks = sm + SM_K;
    uint32_t* __restrict__ Vs = sm + SM_V;
    uint32_t* __restrict__ Ps = sm + SM_P;

    const int bh = blockIdx.y;
    const int q0 = blockIdx.x * 128;
    const float* __restrict__ Q = g_q + (size_t)bh * SS * DD;
    const float* __restrict__ K = g_k + (size_t)bh * SS * DD;
    const float* __restrict__ V = g_v + (size_t)bh * SS * DD;

    const int tid = threadIdx.x;
    const int wid = tid >> 5, lane = tid & 31;
    const int g = lane >> 2, t = lane & 3;
    const int mr = wid * 16;                 // warp's row base within tile

    // Load Q tile (128 x 64) as tf32
#pragma unroll
    for (int i = tid; i < 128 * 16; i += 256) {
        int row = i >> 4, c4 = (i & 15) * 4;
        float4 v = *(const float4*)(Q + (size_t)(q0 + row) * DD + c4);
        Qs[row * QS_STR + c4 + 0] = f2tf32(v.x);
        Qs[row * QS_STR + c4 + 1] = f2tf32(v.y);
        Qs[row * QS_STR + c4 + 2] = f2tf32(v.z);
        Qs[row * QS_STR + c4 + 3] = f2tf32(v.w);
    }

    float accO[8][4];
#pragma unroll
    for (int j = 0; j < 8; j++)
#pragma unroll
        for (int r = 0; r < 4; r++) accO[j][r] = 0.0f;
    float m0 = -1e30f, m1 = -1e30f, l0 = 0.0f, l1 = 0.0f;

    for (int kt = 0; kt < SS; kt += 64) {
        __syncthreads();   // previous iteration's P.V reads done
        // Load K,V tiles (64 x 64 each)
#pragma unroll
        for (int i = tid; i < 64 * 16; i += 256) {
            int row = i >> 4, c4 = (i & 15) * 4;
            float4 kv = *(const float4*)(K + (size_t)(kt + row) * DD + c4);
            Ks[row * KS_STR + c4 + 0] = f2tf32(kv.x);
            Ks[row * KS_STR + c4 + 1] = f2tf32(kv.y);
            Ks[row * KS_STR + c4 + 2] = f2tf32(kv.z);
            Ks[row * KS_STR + c4 + 3] = f2tf32(kv.w);
            float4 vv = *(const float4*)(V + (size_t)(kt + row) * DD + c4);
            Vs[row * VS_STR + c4 + 0] = f2tf32(vv.x);
            Vs[row * VS_STR + c4 + 1] = f2tf32(vv.y);
            Vs[row * VS_STR + c4 + 2] = f2tf32(vv.z);
            Vs[row * VS_STR + c4 + 3] = f2tf32(vv.w);
        }
        __syncthreads();

        // S = Q K^T  (warp tile 16 x 64)
        float accS[8][4];
#pragma unroll
        for (int j = 0; j < 8; j++)
#pragma unroll
            for (int r = 0; r < 4; r++) accS[j][r] = 0.0f;

#pragma unroll
        for (int kb = 0; kb < 8; kb++) {
            uint32_t a[4];
            a[0] = Qs[(mr + g) * QS_STR + kb * 8 + t];
            a[1] = Qs[(mr + g + 8) * QS_STR + kb * 8 + t];
            a[2] = Qs[(mr + g) * QS_STR + kb * 8 + t + 4];
            a[3] = Qs[(mr + g + 8) * QS_STR + kb * 8 + t + 4];
#pragma unroll
            for (int nf = 0; nf < 8; nf++) {
                uint32_t b[2];
                b[0] = Ks[(nf * 8 + g) * KS_STR + kb * 8 + t];
                b[1] = Ks[(nf * 8 + g) * KS_STR + kb * 8 + t + 4];
                mma_tf32(accS[nf], a, b);
            }
        }

        // Online softmax. Rows: mr+g (regs 0,1), mr+g+8 (regs 2,3).
        float r0 = -1e30f, r1 = -1e30f;
#pragma unroll
        for (int nf = 0; nf < 8; nf++) {
            r0 = fmaxf(r0, fmaxf(accS[nf][0], accS[nf][1]));
            r1 = fmaxf(r1, fmaxf(accS[nf][2], accS[nf][3]));
        }
        r0 = fmaxf(r0, __shfl_xor_sync(0xffffffffu, r0, 1));
        r0 = fmaxf(r0, __shfl_xor_sync(0xffffffffu, r0, 2));
        r1 = fmaxf(r1, __shfl_xor_sync(0xffffffffu, r1, 1));
        r1 = fmaxf(r1, __shfl_xor_sync(0xffffffffu, r1, 2));

        float mn0 = fmaxf(m0, 0.125f * r0);
        float mn1 = fmaxf(m1, 0.125f * r1);
        float al0 = __expf(m0 - mn0);
        float al1 = __expf(m1 - mn1);
        m0 = mn0; m1 = mn1;

        float s0 = 0.0f, s1 = 0.0f;
#pragma unroll
        for (int nf = 0; nf < 8; nf++) {
            float p00 = __expf(fmaf(0.125f, accS[nf][0], -m0));
            float p01 = __expf(fmaf(0.125f, accS[nf][1], -m0));
            float p10 = __expf(fmaf(0.125f, accS[nf][2], -m1));
            float p11 = __expf(fmaf(0.125f, accS[nf][3], -m1));
            s0 += p00 + p01;
            s1 += p10 + p11;
            int c = nf * 8 + 2 * t;
            Ps[(mr + g) * PS_STR + c]         = f2tf32(p00);
            Ps[(mr + g) * PS_STR + c + 1]     = f2tf32(p01);
            Ps[(mr + g + 8) * PS_STR + c]     = f2tf32(p10);
            Ps[(mr + g + 8) * PS_STR + c + 1] = f2tf32(p11);
        }
        s0 += __shfl_xor_sync(0xffffffffu, s0, 1);
        s0 += __shfl_xor_sync(0xffffffffu, s0, 2);
        s1 += __shfl_xor_sync(0xffffffffu, s1, 1);
        s1 += __shfl_xor_sync(0xffffffffu, s1, 2);
        l0 = l0 * al0 + s0;
        l1 = l1 * al1 + s1;

#pragma unroll
        for (int nf = 0; nf < 8; nf++) {
            accO[nf][0] *= al0;
            accO[nf][1] *= al0;
            accO[nf][2] *= al1;
            accO[nf][3] *= al1;
        }
        __syncwarp();       // P rows for this warp are warp-private; warp-sync suffices

        // O += P @ V   (contraction over 64 keys)
#pragma unroll
        for (int kb = 0; kb < 8; kb++) {
            uint32_t a[4];
            a[0] = Ps[(mr + g) * PS_STR + kb * 8 + t];
            a[1] = Ps[(mr + g + 8) * PS_STR + kb * 8 + t];
            a[2] = Ps[(mr + g) * PS_STR + kb * 8 + t + 4];
            a[3] = Ps[(mr + g + 8) * PS_STR + kb * 8 + t + 4];
#pragma unroll
            for (int nf = 0; nf < 8; nf++) {
                uint32_t b[2];
                b[0] = Vs[(kb * 8 + t) * VS_STR + nf * 8 + g];
                b[1] = Vs[(kb * 8 + t + 4) * VS_STR + nf * 8 + g];
                mma_tf32(accO[nf], a, b);
            }
        }
    }

    // Epilogue: normalize and write to flat ctx layout
    const float inv0 = 1.0f / l0;
    const float inv1 = 1.0f / l1;
    const int bb = bh >> 4, h = bh & 15;
    const int s0r = q0 + mr + g;
#pragma unroll
    for (int nf = 0; nf < 8; nf++) {
        int d = nf * 8 + 2 * t;
        float2 v0 = { accO[nf][0] * inv0, accO[nf][1] * inv0 };
        float2 v1 = { accO[nf][2] * inv1, accO[nf][3] * inv1 };
        *(float2*)(g_ctx + ((size_t)(bb * SS + s0r)) * HID + h * DD + d) = v0;
        *(float2*)(g_ctx + ((size_t)(bb * SS + s0r + 8)) * HID + h * DD + d) = v1;
    }
}

// ----------------------------------------------------------------------------
// Output projection (TF32 MMA): out = ctx @ Wo + bo. M=4096, N=1024, K=1024.
// ----------------------------------------------------------------------------
__global__ __launch_bounds__(256) void oproj_mma_kernel(
    const float* __restrict__ Wo, const float* __restrict__ bo,
    float* __restrict__ out)
{
    __shared__ uint32_t As[128][20];
    __shared__ uint32_t Bs[16][136];

    const int m0 = blockIdx.y * 128;
    const int n0 = blockIdx.x * 128;
    const int tid = threadIdx.x;
    const int wid = tid >> 5, lane = tid & 31;
    const int g = lane >> 2, t = lane & 3;
    const int wm = wid >> 1, wn = wid & 1;

    float acc[2][8][4];
#pragma unroll
    for (int i = 0; i < 2; i++)
#pragma unroll
        for (int j = 0; j < 8; j++)
#pragma unroll
            for (int r = 0; r < 4; r++) acc[i][j][r] = 0.0f;

    for (int k0 = 0; k0 < HID; k0 += 16) {
#pragma unroll
        for (int i = tid; i < 512; i += 256) {
            int row = i >> 2, c4 = (i & 3) * 4;
            float4 v = *(const float4*)(g_ctx + (size_t)(m0 + row) * HID + k0 + c4);
            As[row][c4 + 0] = f2tf32(v.x);
            As[row][c4 + 1] = f2tf32(v.y);
            As[row][c4 + 2] = f2tf32(v.z);
            As[row][c4 + 3] = f2tf32(v.w);
        }
#pragma unroll
        for (int i = tid; i < 512; i += 256) {
            int kk = i >> 5, n4 = (i & 31) * 4;
            float4 v = *(const float4*)(Wo + (size_t)(k0 + kk) * HID + n0 + n4);
            Bs[kk][n4 + 0] = f2tf32(v.x);
            Bs[kk][n4 + 1] = f2tf32(v.y);
            Bs[kk][n4 + 2] = f2tf32(v.z);
            Bs[kk][n4 + 3] = f2tf32(v.w);
        }
        __syncthreads();

#pragma unroll
        for (int ks = 0; ks < 2; ks++) {
            const int kb = ks * 8;
            uint32_t a[2][4], b[8][2];
#pragma unroll
            for (int ma = 0; ma < 2; ma++) {
                int row = wm * 32 + ma * 16 + g;
                a[ma][0] = As[row][kb + t];
                a[ma][1] = As[row + 8][kb + t];
                a[ma][2] = As[row][kb + t + 4];
                a[ma][3] = As[row + 8][kb + t + 4];
            }
#pragma unroll
            for (int na = 0; na < 8; na++) {
                int n = wn * 64 + na * 8 + g;
                b[na][0] = Bs[kb + t][n];
                b[na][1] = Bs[kb + t + 4][n];
            }
#pragma unroll
            for (int ma = 0; ma < 2; ma++)
#pragma unroll
                for (int na = 0; na < 8; na++)
                    mma_tf32(acc[ma][na], a[ma], b[na]);
        }
        __syncthreads();
    }

#pragma unroll
    for (int ma = 0; ma < 2; ma++) {
#pragma unroll
        for (int na = 0; na < 8; na++) {
            int m = m0 + wm * 32 + ma * 16 + g;
            int n = n0 + wn * 64 + na * 8 + 2 * t;
            float b0 = bo[n], b1 = bo[n + 1];
            float2 v0 = { acc[ma][na][0] + b0, acc[ma][na][1] + b1 };
            float2 v1 = { acc[ma][na][2] + b0, acc[ma][na][3] + b1 };
            *(float2*)(out + (size_t)m * HID + n) = v0;
            *(float2*)(out + (size_t)(m + 8) * HID + n) = v1;
        }
    }
}

// ----------------------------------------------------------------------------
extern "C" void kernel_launch(void* const* d_in, const int* in_sizes, int n_in,
                              void* d_out, int out_size)
{
    const float* X  = (const float*)d_in[0];
    const float* Wq = (const float*)d_in[1];
    const float* bq = (const float*)d_in[2];
    const float* Wk = (const float*)d_in[3];
    const float* bk = (const float*)d_in[4];
    const float* Wv = (const float*)d_in[5];
    const float* bv = (const float*)d_in[6];
    const float* Wo = (const float*)d_in[7];
    const float* bo = (const float*)d_in[8];
    float* out = (float*)d_out;

    static int smem_set = 0;
    if (!smem_set) {
        cudaFuncSetAttribute(flash_kernel,
                             cudaFuncAttributeMaxDynamicSharedMemorySize,
                             FLASH_SMEM_BYTES);
        smem_set = 1;
    }

    qkv_mma_kernel<<<dim3(HID / 128, MM / 128, 3), 256>>>(X, Wq, bq, Wk, bk, Wv, bv);

    {
        const int total = 2 * BH * SS * 30;
        rope_kernel<<<(total + 255) / 256, 256>>>();
    }

    flash_kernel<<<dim3(SS / 128, BH), 256, FLASH_SMEM_BYTES>>>();

    oproj_mma_kernel<<<dim3(HID / 128, MM / 128), 256>>>(Wo, bo, out);
}